// round 1
// baseline (speedup 1.0000x reference)
#include <cuda_runtime.h>
#include <math.h>

typedef unsigned long long ull;

// ---------------- constants ----------------
#define BS_     2048
#define A_      32
#define ROWS    (BS_ * A_)     // 65536
#define IN_DIM  256
#define HID     256
#define NH      4
#define HD      16
#define CV      16
#define TOPK    8
#define NACT    20
#define QKVG_N  196            // 64 q + 64 k + 64 v + 4 g
#define NEGV    (-1e10f)

#define M_NONE 0
#define M_RELU 1
#define M_QKVG 2

// ---------------- scratch (device globals; no allocation) ----------------
__device__ float g_x   [ROWS * HID];        // relu(fc1)
__device__ float g_gi  [ROWS * 3 * HID];    // x @ W_ih^T + b_ih
__device__ float g_gh  [ROWS * 3 * HID];    // h @ W_hh^T + b_hh
__device__ float g_qkvg[ROWS * QKVG_N];     // packed q|k|v|sig(g)
__device__ float g_msg [ROWS * (NH * CV)];  // gated messages (64)
__device__ float g_p1  [ROWS * HID];        // relu(p1)
__device__ float g_wq  [QKVG_N * HID];      // packed qkvg weights
__device__ float g_bq  [QKVG_N];            // packed qkvg bias

// ---------------- f32x2 helpers ----------------
__device__ __forceinline__ ull pk2(float x) {
    ull r; asm("mov.b64 %0, {%1, %1};" : "=l"(r) : "f"(x)); return r;
}
__device__ __forceinline__ ull pk(float x, float y) {
    ull r; asm("mov.b64 %0, {%1, %2};" : "=l"(r) : "f"(x), "f"(y)); return r;
}
__device__ __forceinline__ void fma2(ull& d, ull a, ull b) {
    asm("fma.rn.f32x2 %0, %1, %2, %0;" : "+l"(d) : "l"(a), "l"(b));
}
__device__ __forceinline__ void unpk(ull v, float& x, float& y) {
    asm("mov.b64 {%0, %1}, %2;" : "=f"(x), "=f"(y) : "l"(v));
}

__device__ __forceinline__ float sigmoidf_(float x) { return 1.0f / (1.0f + expf(-x)); }

// ---------------- generic tiled GEMM: C[M,N] = A[M,K] @ B[N,K]^T + bias ----------------
// Split-A: rows read from A1 for k < K1 (stride lda1), else A2 at (k-K1) (stride lda2).
// K1 must be a multiple of BK. M multiple of 64. K multiple of 32. N arbitrary (guarded).
#define BM 64
#define BN 64
#define BK 32

__global__ __launch_bounds__(256) void gemm_kernel(
    const float* __restrict__ A1, const float* __restrict__ A2, int K1, int lda1, int lda2,
    const float* __restrict__ B, const float* __restrict__ bias,
    float* __restrict__ C, int ldc, int N, int K, int mode)
{
    __shared__ __align__(16) float As[BM][BK + 1];  // 64 x 33 (conflict-free scalar a loads)
    __shared__ __align__(16) float Bs[BK][BN + 4];  // 32 x 68 (aligned float4 b loads)

    const int tid = threadIdx.x;
    const int m0 = blockIdx.y * BM;
    const int n0 = blockIdx.x * BN;
    const int tx = tid & 15;        // col group (16)
    const int ty = tid >> 4;        // row group (16)

    ull acc[4][2];
#pragma unroll
    for (int i = 0; i < 4; i++) { acc[i][0] = 0ull; acc[i][1] = 0ull; }

    for (int k0 = 0; k0 < K; k0 += BK) {
        // load A tile (64 rows x 32 k), coalesced float4 along k
#pragma unroll
        for (int r = 0; r < 2; r++) {
            int e   = tid + r * 256;
            int row = e >> 3;
            int kq  = (e & 7) * 4;
            int kg  = k0 + kq;
            const float* src;
            if (kg < K1) src = A1 + (size_t)(m0 + row) * lda1 + kg;
            else         src = A2 + (size_t)(m0 + row) * lda2 + (kg - K1);
            float4 v = *(const float4*)src;
            As[row][kq + 0] = v.x; As[row][kq + 1] = v.y;
            As[row][kq + 2] = v.z; As[row][kq + 3] = v.w;
        }
        // load B tile (64 cols x 32 k), transpose into Bs[k][col]
#pragma unroll
        for (int r = 0; r < 2; r++) {
            int e   = tid + r * 256;
            int col = e >> 3;
            int kq  = (e & 7) * 4;
            float4 v = make_float4(0.f, 0.f, 0.f, 0.f);
            if (n0 + col < N) v = *(const float4*)(B + (size_t)(n0 + col) * K + k0 + kq);
            Bs[kq + 0][col] = v.x; Bs[kq + 1][col] = v.y;
            Bs[kq + 2][col] = v.z; Bs[kq + 3][col] = v.w;
        }
        __syncthreads();

#pragma unroll
        for (int kk = 0; kk < BK; kk++) {
            float4 b4 = *(const float4*)&Bs[kk][tx * 4];
            ull b01 = pk(b4.x, b4.y);
            ull b23 = pk(b4.z, b4.w);
#pragma unroll
            for (int i = 0; i < 4; i++) {
                ull aa = pk2(As[ty * 4 + i][kk]);
                fma2(acc[i][0], aa, b01);
                fma2(acc[i][1], aa, b23);
            }
        }
        __syncthreads();
    }

    // epilogue
#pragma unroll
    for (int i = 0; i < 4; i++) {
        int row = m0 + ty * 4 + i;
#pragma unroll
        for (int p = 0; p < 2; p++) {
            float lo, hi;
            unpk(acc[i][p], lo, hi);
            float vals[2] = {lo, hi};
#pragma unroll
            for (int j = 0; j < 2; j++) {
                int col = n0 + tx * 4 + p * 2 + j;
                if (col < N) {
                    float v = vals[j] + bias[col];
                    if (mode == M_RELU) v = fmaxf(v, 0.f);
                    else if (mode == M_QKVG && col >= 192) v = sigmoidf_(v);
                    C[(size_t)row * ldc + col] = v;
                }
            }
        }
    }
}

// ---------------- pack q/k/v/g weights+bias into one [196,256] matrix ----------------
__global__ void pack_qkvg(const float* __restrict__ qw, const float* __restrict__ qb,
                          const float* __restrict__ kw, const float* __restrict__ kb,
                          const float* __restrict__ vw, const float* __restrict__ vb,
                          const float* __restrict__ gw, const float* __restrict__ gb)
{
    int i = blockIdx.x * blockDim.x + threadIdx.x;
    const int total = QKVG_N * HID;
    if (i < total) {
        int row = i / HID, c = i - row * HID;
        float v;
        if      (row < 64)  v = qw[row * HID + c];
        else if (row < 128) v = kw[(row - 64) * HID + c];
        else if (row < 192) v = vw[(row - 128) * HID + c];
        else                v = gw[(row - 192) * HID + c];
        g_wq[i] = v;
    }
    if (i < QKVG_N) {
        float b;
        if      (i < 64)  b = qb[i];
        else if (i < 128) b = kb[i - 64];
        else if (i < 192) b = vb[i - 128];
        else              b = gb[i - 192];
        g_bq[i] = b;
    }
}

// ---------------- GRU gate fusion: h = (1-z)*n + z*h_in ----------------
__global__ void gru_gates(const float* __restrict__ gi, const float* __restrict__ gh,
                          const float* __restrict__ hin, float* __restrict__ hout)
{
    int i4 = blockIdx.x * blockDim.x + threadIdx.x;   // over ROWS*64 float4s
    if (i4 >= ROWS * (HID / 4)) return;
    int row = i4 >> 6;
    int c   = (i4 & 63) << 2;
    const float* gib = gi + (size_t)row * 768 + c;
    const float* ghb = gh + (size_t)row * 768 + c;
    float4 gir = *(const float4*)(gib);
    float4 giz = *(const float4*)(gib + 256);
    float4 gin = *(const float4*)(gib + 512);
    float4 ghr = *(const float4*)(ghb);
    float4 ghz = *(const float4*)(ghb + 256);
    float4 ghn = *(const float4*)(ghb + 512);
    float4 h0  = *(const float4*)(hin + (size_t)row * HID + c);
    float4 o;
    {
        float r = sigmoidf_(gir.x + ghr.x);
        float z = sigmoidf_(giz.x + ghz.x);
        float n = tanhf(gin.x + r * ghn.x);
        o.x = (1.f - z) * n + z * h0.x;
    }
    {
        float r = sigmoidf_(gir.y + ghr.y);
        float z = sigmoidf_(giz.y + ghz.y);
        float n = tanhf(gin.y + r * ghn.y);
        o.y = (1.f - z) * n + z * h0.y;
    }
    {
        float r = sigmoidf_(gir.z + ghr.z);
        float z = sigmoidf_(giz.z + ghz.z);
        float n = tanhf(gin.z + r * ghn.z);
        o.z = (1.f - z) * n + z * h0.z;
    }
    {
        float r = sigmoidf_(gir.w + ghr.w);
        float z = sigmoidf_(giz.w + ghz.w);
        float n = tanhf(gin.w + r * ghn.w);
        o.w = (1.f - z) * n + z * h0.w;
    }
    *(float4*)(hout + (size_t)row * HID + c) = o;
}

// ---------------- per-batch sparse attention ----------------
// block = one batch element (32 agents), 128 threads = (agent, head) pairs.
__global__ __launch_bounds__(128) void attention_kernel(const float* __restrict__ qkvg,
                                                        float* __restrict__ msg)
{
    __shared__ float q_s[A_][64];
    __shared__ float k_s[A_][64];
    __shared__ float v_s[A_][64];
    __shared__ float g_s[A_][NH];

    const int b = blockIdx.x;
    const int tid = threadIdx.x;
    const float* base = qkvg + (size_t)b * A_ * QKVG_N;

    for (int idx = tid; idx < A_ * QKVG_N; idx += 128) {
        int r = idx / QKVG_N, c = idx - r * QKVG_N;
        float v = base[(size_t)r * QKVG_N + c];
        if      (c < 64)  q_s[r][c] = v;
        else if (c < 128) k_s[r][c - 64] = v;
        else if (c < 192) v_s[r][c - 128] = v;
        else              g_s[r][c - 192] = v;
    }
    __syncthreads();

    const int qa = tid >> 2;
    const int hh = tid & 3;
    const int hb = hh * HD;

    float qv[HD];
#pragma unroll
    for (int d = 0; d < HD; d++) qv[d] = q_s[qa][hb + d];

    float sc[A_];
#pragma unroll
    for (int ka = 0; ka < A_; ka++) {
        float s = 0.f;
#pragma unroll
        for (int d = 0; d < HD; d++) s += qv[d] * k_s[ka][hb + d];
        sc[ka] = (ka == qa) ? NEGV : s * 0.25f;   // 1/sqrt(16)
    }

    // exact lax.top_k: 8 strict-greater argmax passes (ties -> lowest index)
    unsigned sel = 0;
    float maxv = NEGV;
    for (int it = 0; it < TOPK; it++) {
        float best = -INFINITY; int bi = 0;
#pragma unroll
        for (int ka = 0; ka < A_; ka++) {
            bool free_ = !((sel >> ka) & 1u);
            if (free_ && sc[ka] > best) { best = sc[ka]; bi = ka; }
        }
        sel |= (1u << bi);
        if (it == 0) maxv = best;
    }

    float sum = 0.f;
#pragma unroll
    for (int ka = 0; ka < A_; ka++) {
        float e = ((sel >> ka) & 1u) ? expf(sc[ka] - maxv) : 0.f;
        sc[ka] = e;
        sum += e;
    }
    float inv = 1.f / sum;

    float m[CV];
#pragma unroll
    for (int d = 0; d < CV; d++) m[d] = 0.f;
#pragma unroll
    for (int ka = 0; ka < A_; ka++) {
        float w = sc[ka];
#pragma unroll
        for (int d = 0; d < CV; d++) m[d] += w * v_s[ka][hb + d];
    }

    float gate = g_s[qa][hh];   // sigmoid already applied in GEMM epilogue
    float* out = msg + ((size_t)(b * A_ + qa)) * (NH * CV) + hb;
#pragma unroll
    for (int d = 0; d < CV; d++) out[d] = m[d] * inv * gate;
}

// ---------------- launch ----------------
extern "C" void kernel_launch(void* const* d_in, const int* in_sizes, int n_in,
                              void* d_out, int out_size)
{
    const float* inputs = (const float*)d_in[0];
    const float* hidden = (const float*)d_in[1];
    const float* fc1_w  = (const float*)d_in[2];
    const float* fc1_b  = (const float*)d_in[3];
    const float* w_ih   = (const float*)d_in[4];
    const float* w_hh   = (const float*)d_in[5];
    const float* b_ih   = (const float*)d_in[6];
    const float* b_hh   = (const float*)d_in[7];
    const float* q_w    = (const float*)d_in[8];
    const float* q_b    = (const float*)d_in[9];
    const float* k_w    = (const float*)d_in[10];
    const float* k_b    = (const float*)d_in[11];
    const float* v_w    = (const float*)d_in[12];
    const float* v_b    = (const float*)d_in[13];
    const float* g_w    = (const float*)d_in[14];
    const float* g_b    = (const float*)d_in[15];
    const float* p1_w   = (const float*)d_in[16];
    const float* p1_b   = (const float*)d_in[17];
    const float* p2_w   = (const float*)d_in[18];
    const float* p2_b   = (const float*)d_in[19];

    float* out    = (float*)d_out;
    float* logits = out;                      // [65536, 20]
    float* hout   = out + (size_t)ROWS * NACT; // [65536, 256]

    float *x, *gi, *gh, *qkvg, *msg, *p1, *wq, *bq;
    cudaGetSymbolAddress((void**)&x,    g_x);
    cudaGetSymbolAddress((void**)&gi,   g_gi);
    cudaGetSymbolAddress((void**)&gh,   g_gh);
    cudaGetSymbolAddress((void**)&qkvg, g_qkvg);
    cudaGetSymbolAddress((void**)&msg,  g_msg);
    cudaGetSymbolAddress((void**)&p1,   g_p1);
    cudaGetSymbolAddress((void**)&wq,   g_wq);
    cudaGetSymbolAddress((void**)&bq,   g_bq);

    const int MY = ROWS / BM;   // 1024

    pack_qkvg<<<(QKVG_N * HID + 255) / 256, 256>>>(q_w, q_b, k_w, k_b, v_w, v_b, g_w, g_b);

    // x = relu(inputs @ fc1_w^T + fc1_b)
    gemm_kernel<<<dim3(HID / BN, MY), 256>>>(inputs, inputs, IN_DIM, IN_DIM, IN_DIM,
                                             fc1_w, fc1_b, x, HID, HID, IN_DIM, M_RELU);
    // gi = x @ w_ih^T + b_ih ; gh = hidden @ w_hh^T + b_hh
    gemm_kernel<<<dim3(3 * HID / BN, MY), 256>>>(x, x, HID, HID, HID,
                                                 w_ih, b_ih, gi, 3 * HID, 3 * HID, HID, M_NONE);
    gemm_kernel<<<dim3(3 * HID / BN, MY), 256>>>(hidden, hidden, HID, HID, HID,
                                                 w_hh, b_hh, gh, 3 * HID, 3 * HID, HID, M_NONE);
    // h
    gru_gates<<<(ROWS * (HID / 4) + 255) / 256, 256>>>(gi, gh, hidden, hout);
    // q|k|v|sig(g)
    gemm_kernel<<<dim3((QKVG_N + BN - 1) / BN, MY), 256>>>(hout, hout, HID, HID, HID,
                                                           wq, bq, qkvg, QKVG_N, QKVG_N, HID, M_QKVG);
    // sparse attention -> gated messages
    attention_kernel<<<BS_, 128>>>(qkvg, msg);
    // p1 = relu([h | msg] @ p1_w^T + p1_b)   (split-A, K=320)
    gemm_kernel<<<dim3(HID / BN, MY), 256>>>(hout, msg, HID, HID, NH * CV,
                                             p1_w, p1_b, p1, HID, HID, HID + NH * CV, M_RELU);
    // logits = p1 @ p2_w^T + p2_b
    gemm_kernel<<<dim3(1, MY), 256>>>(p1, p1, HID, HID, HID,
                                      p2_w, p2_b, logits, NACT, NACT, HID, M_NONE);
}

// round 3
// speedup vs baseline: 1.2147x; 1.2147x over previous
#include <cuda_runtime.h>
#include <math.h>

typedef unsigned long long ull;

// ---------------- constants ----------------
#define BS_     2048
#define A_      32
#define ROWS    (BS_ * A_)     // 65536
#define IN_DIM  256
#define HID     256
#define NH      4
#define HD      16
#define CV      16
#define TOPK    8
#define NACT    20
#define QKVG_N  196            // 64 q + 64 k + 64 v + 4 g
#define NEGV    (-1e10f)

#define M_NONE 0
#define M_RELU 1
#define M_QKVG 2

// ---------------- scratch (device globals; no allocation) ----------------
__device__ float g_x   [ROWS * HID];        // relu(fc1)
__device__ float g_gi  [ROWS * 3 * HID];    // x @ W_ih^T + b_ih
__device__ float g_gh  [ROWS * 3 * HID];    // h @ W_hh^T + b_hh
__device__ float g_qkvg[ROWS * QKVG_N];     // packed q|k|v|sig(g)
__device__ float g_msg [ROWS * (NH * CV)];  // gated messages (64)
__device__ float g_p1  [ROWS * HID];        // relu(p1)
__device__ float g_wq  [QKVG_N * HID];      // packed qkvg weights
__device__ float g_bq  [QKVG_N];            // packed qkvg bias

// ---------------- f32x2 helpers ----------------
__device__ __forceinline__ ull pk2(float x) {
    ull r; asm("mov.b64 %0, {%1, %1};" : "=l"(r) : "f"(x)); return r;
}
__device__ __forceinline__ ull pk(float x, float y) {
    ull r; asm("mov.b64 %0, {%1, %2};" : "=l"(r) : "f"(x), "f"(y)); return r;
}
__device__ __forceinline__ void fma2(ull& d, ull a, ull b) {
    asm("fma.rn.f32x2 %0, %1, %2, %0;" : "+l"(d) : "l"(a), "l"(b));
}
__device__ __forceinline__ void unpk(ull v, float& x, float& y) {
    asm("mov.b64 {%0, %1}, %2;" : "=f"(x), "=f"(y) : "l"(v));
}

__device__ __forceinline__ float sigmoidf_(float x) { return 1.0f / (1.0f + expf(-x)); }

// ---------------- 8x8 register-blocked GEMM ----------------
// C[M,N] = A[M,K] @ B[N,K]^T + bias, optional fused activation.
// Split-A: k < K1 reads A1 (stride lda1), else A2 at (k-K1) (stride lda2).
// BM=128 fixed, BN template (128 or 64). K multiple of 16, K1 multiple of 4.
// 256 threads, each computes 8 rows x TN cols (TN = BN/16).
#define BM 128
#define BK 16

template<int BN>
__global__ __launch_bounds__(256, 2) void gemm8x8(
    const float* __restrict__ A1, const float* __restrict__ A2, int K1, int lda1, int lda2,
    const float* __restrict__ B, const float* __restrict__ bias,
    float* __restrict__ C, int ldc, int N, int K, int mode)
{
    constexpr int TN  = BN / 16;      // 8 or 4 cols per thread
    constexpr int PAD = 4;
    __shared__ __align__(16) float As[BK][BM + PAD];  // k-major, 16B-aligned rows
    __shared__ __align__(16) float Bs[BK][BN + PAD];

    const int tid = threadIdx.x;
    const int m0 = blockIdx.y * BM;
    const int n0 = blockIdx.x * BN;
    const int tx = tid & 15;          // col group
    const int ty = tid >> 4;          // row group

    ull acc[8][TN / 2];
#pragma unroll
    for (int i = 0; i < 8; i++)
#pragma unroll
        for (int p = 0; p < TN / 2; p++) acc[i][p] = 0ull;

    for (int k0 = 0; k0 < K; k0 += BK) {
        // ---- load A tile: 128 rows x 16 k, float4 along k, transpose to k-major
#pragma unroll
        for (int r = 0; r < 2; r++) {
            int e   = tid + r * 256;
            int row = e >> 2;
            int kq  = (e & 3) * 4;
            int kg  = k0 + kq;
            const float* src;
            if (kg < K1) src = A1 + (size_t)(m0 + row) * lda1 + kg;
            else         src = A2 + (size_t)(m0 + row) * lda2 + (kg - K1);
            float4 v = *(const float4*)src;
            As[kq + 0][row] = v.x; As[kq + 1][row] = v.y;
            As[kq + 2][row] = v.z; As[kq + 3][row] = v.w;
        }
        // ---- load B tile: BN cols x 16 k, transpose to k-major
#pragma unroll
        for (int r = 0; r < BN / 64; r++) {
            int e   = tid + r * 256;
            int col = e >> 2;
            int kq  = (e & 3) * 4;
            float4 v = make_float4(0.f, 0.f, 0.f, 0.f);
            if (n0 + col < N) v = *(const float4*)(B + (size_t)(n0 + col) * K + k0 + kq);
            Bs[kq + 0][col] = v.x; Bs[kq + 1][col] = v.y;
            Bs[kq + 2][col] = v.z; Bs[kq + 3][col] = v.w;
        }
        __syncthreads();

#pragma unroll
        for (int kk = 0; kk < BK; kk++) {
            float4 a0 = *(const float4*)&As[kk][ty * 8];
            float4 a1 = *(const float4*)&As[kk][ty * 8 + 4];
            float am[8] = {a0.x, a0.y, a0.z, a0.w, a1.x, a1.y, a1.z, a1.w};

            float bn_[TN];
#pragma unroll
            for (int q = 0; q < TN / 4; q++) {
                float4 b = *(const float4*)&Bs[kk][tx * TN + q * 4];
                bn_[q * 4 + 0] = b.x; bn_[q * 4 + 1] = b.y;
                bn_[q * 4 + 2] = b.z; bn_[q * 4 + 3] = b.w;
            }
            ull bp[TN / 2];
#pragma unroll
            for (int p = 0; p < TN / 2; p++) bp[p] = pk(bn_[2 * p], bn_[2 * p + 1]);

#pragma unroll
            for (int i = 0; i < 8; i++) {
                ull aa = pk2(am[i]);
#pragma unroll
                for (int p = 0; p < TN / 2; p++) fma2(acc[i][p], aa, bp[p]);
            }
        }
        __syncthreads();
    }

    // ---- epilogue
    float bias_r[TN];
#pragma unroll
    for (int j = 0; j < TN; j++) {
        int col = n0 + tx * TN + j;
        bias_r[j] = (col < N) ? bias[col] : 0.f;
    }

    const bool full = (n0 + BN <= N);
#pragma unroll
    for (int i = 0; i < 8; i++) {
        int row = m0 + ty * 8 + i;
        float vals[TN];
#pragma unroll
        for (int p = 0; p < TN / 2; p++) unpk(acc[i][p], vals[2 * p], vals[2 * p + 1]);
#pragma unroll
        for (int j = 0; j < TN; j++) {
            int col = n0 + tx * TN + j;
            float v = vals[j] + bias_r[j];
            if (mode == M_RELU) v = fmaxf(v, 0.f);
            else if (mode == M_QKVG && col >= 192) v = sigmoidf_(v);
            vals[j] = v;
        }
        if (full) {
            float* dst = C + (size_t)row * ldc + n0 + tx * TN;
#pragma unroll
            for (int q = 0; q < TN / 4; q++) {
                float4 o = make_float4(vals[q * 4 + 0], vals[q * 4 + 1],
                                       vals[q * 4 + 2], vals[q * 4 + 3]);
                *(float4*)(dst + q * 4) = o;
            }
        } else {
#pragma unroll
            for (int j = 0; j < TN; j++) {
                int col = n0 + tx * TN + j;
                if (col < N) C[(size_t)row * ldc + col] = vals[j];
            }
        }
    }
}

// ---------------- pack q/k/v/g weights+bias into one [196,256] matrix ----------------
__global__ void pack_qkvg(const float* __restrict__ qw, const float* __restrict__ qb,
                          const float* __restrict__ kw, const float* __restrict__ kb,
                          const float* __restrict__ vw, const float* __restrict__ vb,
                          const float* __restrict__ gw, const float* __restrict__ gb)
{
    int i = blockIdx.x * blockDim.x + threadIdx.x;
    const int total = QKVG_N * HID;
    if (i < total) {
        int row = i / HID, c = i - row * HID;
        float v;
        if      (row < 64)  v = qw[row * HID + c];
        else if (row < 128) v = kw[(row - 64) * HID + c];
        else if (row < 192) v = vw[(row - 128) * HID + c];
        else                v = gw[(row - 192) * HID + c];
        g_wq[i] = v;
    }
    if (i < QKVG_N) {
        float b;
        if      (i < 64)  b = qb[i];
        else if (i < 128) b = kb[i - 64];
        else if (i < 192) b = vb[i - 128];
        else              b = gb[i - 192];
        g_bq[i] = b;
    }
}

// ---------------- GRU gate fusion: h = (1-z)*n + z*h_in ----------------
__global__ void gru_gates(const float* __restrict__ gi, const float* __restrict__ gh,
                          const float* __restrict__ hin, float* __restrict__ hout)
{
    int i4 = blockIdx.x * blockDim.x + threadIdx.x;   // over ROWS*64 float4s
    if (i4 >= ROWS * (HID / 4)) return;
    int row = i4 >> 6;
    int c   = (i4 & 63) << 2;
    const float* gib = gi + (size_t)row * 768 + c;
    const float* ghb = gh + (size_t)row * 768 + c;
    float4 gir = *(const float4*)(gib);
    float4 giz = *(const float4*)(gib + 256);
    float4 gin = *(const float4*)(gib + 512);
    float4 ghr = *(const float4*)(ghb);
    float4 ghz = *(const float4*)(ghb + 256);
    float4 ghn = *(const float4*)(ghb + 512);
    float4 h0  = *(const float4*)(hin + (size_t)row * HID + c);
    float4 o;
    {
        float r = sigmoidf_(gir.x + ghr.x);
        float z = sigmoidf_(giz.x + ghz.x);
        float n = tanhf(gin.x + r * ghn.x);
        o.x = (1.f - z) * n + z * h0.x;
    }
    {
        float r = sigmoidf_(gir.y + ghr.y);
        float z = sigmoidf_(giz.y + ghz.y);
        float n = tanhf(gin.y + r * ghn.y);
        o.y = (1.f - z) * n + z * h0.y;
    }
    {
        float r = sigmoidf_(gir.z + ghr.z);
        float z = sigmoidf_(giz.z + ghz.z);
        float n = tanhf(gin.z + r * ghn.z);
        o.z = (1.f - z) * n + z * h0.z;
    }
    {
        float r = sigmoidf_(gir.w + ghr.w);
        float z = sigmoidf_(giz.w + ghz.w);
        float n = tanhf(gin.w + r * ghn.w);
        o.w = (1.f - z) * n + z * h0.w;
    }
    *(float4*)(hout + (size_t)row * HID + c) = o;
}

// ---------------- per-batch sparse attention ----------------
__global__ __launch_bounds__(128) void attention_kernel(const float* __restrict__ qkvg,
                                                        float* __restrict__ msg)
{
    __shared__ float q_s[A_][64];
    __shared__ float k_s[A_][64];
    __shared__ float v_s[A_][64];
    __shared__ float g_s[A_][NH];

    const int b = blockIdx.x;
    const int tid = threadIdx.x;
    const float* base = qkvg + (size_t)b * A_ * QKVG_N;

    for (int idx = tid; idx < A_ * QKVG_N; idx += 128) {
        int r = idx / QKVG_N, c = idx - r * QKVG_N;
        float v = base[(size_t)r * QKVG_N + c];
        if      (c < 64)  q_s[r][c] = v;
        else if (c < 128) k_s[r][c - 64] = v;
        else if (c < 192) v_s[r][c - 128] = v;
        else              g_s[r][c - 192] = v;
    }
    __syncthreads();

    const int qa = tid >> 2;
    const int hh = tid & 3;
    const int hb = hh * HD;

    float qv[HD];
#pragma unroll
    for (int d = 0; d < HD; d++) qv[d] = q_s[qa][hb + d];

    float sc[A_];
#pragma unroll
    for (int ka = 0; ka < A_; ka++) {
        float s = 0.f;
#pragma unroll
        for (int d = 0; d < HD; d++) s += qv[d] * k_s[ka][hb + d];
        sc[ka] = (ka == qa) ? NEGV : s * 0.25f;   // 1/sqrt(16)
    }

    // exact lax.top_k: 8 strict-greater argmax passes (ties -> lowest index)
    unsigned sel = 0;
    float maxv = NEGV;
    for (int it = 0; it < TOPK; it++) {
        float best = -INFINITY; int bi = 0;
#pragma unroll
        for (int ka = 0; ka < A_; ka++) {
            bool free_ = !((sel >> ka) & 1u);
            if (free_ && sc[ka] > best) { best = sc[ka]; bi = ka; }
        }
        sel |= (1u << bi);
        if (it == 0) maxv = best;
    }

    float sum = 0.f;
#pragma unroll
    for (int ka = 0; ka < A_; ka++) {
        float e = ((sel >> ka) & 1u) ? expf(sc[ka] - maxv) : 0.f;
        sc[ka] = e;
        sum += e;
    }
    float inv = 1.f / sum;

    float m[CV];
#pragma unroll
    for (int d = 0; d < CV; d++) m[d] = 0.f;
#pragma unroll
    for (int ka = 0; ka < A_; ka++) {
        float w = sc[ka];
#pragma unroll
        for (int d = 0; d < CV; d++) m[d] += w * v_s[ka][hb + d];
    }

    float gate = g_s[qa][hh];
    float* out = msg + ((size_t)(b * A_ + qa)) * (NH * CV) + hb;
#pragma unroll
    for (int d = 0; d < CV; d++) out[d] = m[d] * inv * gate;
}

// ---------------- launch ----------------
extern "C" void kernel_launch(void* const* d_in, const int* in_sizes, int n_in,
                              void* d_out, int out_size)
{
    const float* inputs = (const float*)d_in[0];
    const float* hidden = (const float*)d_in[1];
    const float* fc1_w  = (const float*)d_in[2];
    const float* fc1_b  = (const float*)d_in[3];
    const float* w_ih   = (const float*)d_in[4];
    const float* w_hh   = (const float*)d_in[5];
    const float* b_ih   = (const float*)d_in[6];
    const float* b_hh   = (const float*)d_in[7];
    const float* q_w    = (const float*)d_in[8];
    const float* q_b    = (const float*)d_in[9];
    const float* k_w    = (const float*)d_in[10];
    const float* k_b    = (const float*)d_in[11];
    const float* v_w    = (const float*)d_in[12];
    const float* v_b    = (const float*)d_in[13];
    const float* g_w    = (const float*)d_in[14];
    const float* g_b    = (const float*)d_in[15];
    const float* p1_w   = (const float*)d_in[16];
    const float* p1_b   = (const float*)d_in[17];
    const float* p2_w   = (const float*)d_in[18];
    const float* p2_b   = (const float*)d_in[19];

    float* out    = (float*)d_out;
    float* logits = out;                       // [65536, 20]
    float* hout   = out + (size_t)ROWS * NACT; // [65536, 256]

    float *x, *gi, *gh, *qkvg, *msg, *p1, *wq, *bq;
    cudaGetSymbolAddress((void**)&x,    g_x);
    cudaGetSymbolAddress((void**)&gi,   g_gi);
    cudaGetSymbolAddress((void**)&gh,   g_gh);
    cudaGetSymbolAddress((void**)&qkvg, g_qkvg);
    cudaGetSymbolAddress((void**)&msg,  g_msg);
    cudaGetSymbolAddress((void**)&p1,   g_p1);
    cudaGetSymbolAddress((void**)&wq,   g_wq);
    cudaGetSymbolAddress((void**)&bq,   g_bq);

    const int MY = ROWS / BM;   // 512

    pack_qkvg<<<(QKVG_N * HID + 255) / 256, 256>>>(q_w, q_b, k_w, k_b, v_w, v_b, g_w, g_b);

    // x = relu(inputs @ fc1_w^T + fc1_b)
    gemm8x8<128><<<dim3(HID / 128, MY), 256>>>(inputs, inputs, IN_DIM, IN_DIM, IN_DIM,
                                               fc1_w, fc1_b, x, HID, HID, IN_DIM, M_RELU);
    // gi = x @ w_ih^T + b_ih ; gh = hidden @ w_hh^T + b_hh
    gemm8x8<128><<<dim3(3 * HID / 128, MY), 256>>>(x, x, HID, HID, HID,
                                                   w_ih, b_ih, gi, 3 * HID, 3 * HID, HID, M_NONE);
    gemm8x8<128><<<dim3(3 * HID / 128, MY), 256>>>(hidden, hidden, HID, HID, HID,
                                                   w_hh, b_hh, gh, 3 * HID, 3 * HID, HID, M_NONE);
    // h
    gru_gates<<<(ROWS * (HID / 4) + 255) / 256, 256>>>(gi, gh, hidden, hout);
    // q|k|v|sig(g)
    gemm8x8<128><<<dim3((QKVG_N + 127) / 128, MY), 256>>>(hout, hout, HID, HID, HID,
                                                          wq, bq, qkvg, QKVG_N, QKVG_N, HID, M_QKVG);
    // sparse attention -> gated messages
    attention_kernel<<<BS_, 128>>>(qkvg, msg);
    // p1 = relu([h | msg] @ p1_w^T + p1_b)   (split-A, K=320)
    gemm8x8<128><<<dim3(HID / 128, MY), 256>>>(hout, msg, HID, HID, NH * CV,
                                               p1_w, p1_b, p1, HID, HID, HID + NH * CV, M_RELU);
    // logits = p1 @ p2_w^T + p2_b  (BN=64, N=20)
    gemm8x8<64><<<dim3(1, MY), 256>>>(p1, p1, HID, HID, HID,
                                      p2_w, p2_b, logits, NACT, NACT, HID, M_NONE);
}